// round 10
// baseline (speedup 1.0000x reference)
#include <cuda_runtime.h>
#include <cuda_bf16.h>
#include <cstdint>

#define EDIM 64
#define NDIM 128
#define TM   128            // edges per tile
#define THREADS 512
#define MAXNODES 65536
#define LN_EPS 1e-5f

// ---- dynamic smem layout (bytes) ----
#define OFF_WHI   0         // W^T hi: 128 n-rows x 128B (64 bf16 k)
#define OFF_WLO   16384
#define OFF_A     32768     // A[2 buf][hi|lo], each part 16384
#define ABUF      32768
#define APART     16384
#define OFF_SH    98304     // float[128][128] C (swizzled cols)
#define OFF_SIDX  163840    // int[2][256]
#define OFF_BIAS  165888    // float[128]
#define OFF_SPART 166400    // float2[128][2]
#define SMEM_TOTAL 168448

#define SWZ(x) ((x) ^ (((x) >> 3) & 0x70))

#define LDMX4(r, addr) \
    asm volatile("ldmatrix.sync.aligned.m8n8.x4.shared.b16 {%0,%1,%2,%3}, [%4];" \
        : "=r"((r)[0]), "=r"((r)[1]), "=r"((r)[2]), "=r"((r)[3]) : "r"(addr))

#define MMA16816(c, a, b0, b1) \
    asm volatile("mma.sync.aligned.m16n8k16.row.col.f32.bf16.bf16.f32 " \
        "{%0,%1,%2,%3}, {%4,%5,%6,%7}, {%8,%9}, {%0,%1,%2,%3};" \
        : "+f"((c)[0]), "+f"((c)[1]), "+f"((c)[2]), "+f"((c)[3]) \
        : "r"((a)[0]), "r"((a)[1]), "r"((a)[2]), "r"((a)[3]), "r"(b0), "r"(b1))

#define RED4(ptr, v) \
    asm volatile("red.global.add.v4.f32 [%0], {%1,%2,%3,%4};" \
                 :: "l"(ptr), "f"((v).x), "f"((v).y), "f"((v).z), "f"((v).w) : "memory")

__device__ __forceinline__ uint32_t smem_u32(const void* p) {
    uint32_t a;
    asm("{ .reg .u64 t; cvta.to.shared.u64 t, %1; cvt.u32.u64 %0, t; }" : "=r"(a) : "l"(p));
    return a;
}
__device__ __forceinline__ uint32_t bf2u(__nv_bfloat162 h) {
    return *reinterpret_cast<uint32_t*>(&h);
}

__device__ float g_degree[MAXNODES];

__global__ void zero_kernel(float4* __restrict__ out, int n_out4, int n_nodes) {
    int i = blockIdx.x * blockDim.x + threadIdx.x;
    int stride = gridDim.x * blockDim.x;
    float4 z = make_float4(0.f, 0.f, 0.f, 0.f);
    for (int j = i; j < n_out4; j += stride) out[j] = z;
    for (int j = i; j < n_nodes; j += stride) g_degree[j] = 0.f;
}
__global__ void noop_kernel() {}

// stage tile tt into A buffer bb (hi/lo bf16 split, SWZ layout); indices + degree
__device__ __forceinline__ void stage_tile(
    char* sm, const float* __restrict__ edge_attr, const int* __restrict__ eidx,
    int tt, int bb, int E, int n_tiles, int n_nodes, int tid)
{
    if (tt >= n_tiles) return;
    const int base = tt * TM;
    const int nE = min(TM, E - base);
    char* ahi = sm + OFF_A + bb * ABUF;
    char* alo = ahi + APART;
#pragma unroll
    for (int ci = 0; ci < 2; ci++) {
        int c = tid + THREADS * ci;          // 0..1023 chunks of 8 floats
        int eL = c >> 3, k8 = c & 7;
        float4 f0 = make_float4(0.f, 0.f, 0.f, 0.f), f1 = f0;
        if (eL < nE) {
            const float4* p = (const float4*)(edge_attr + (long long)(base + eL) * EDIM + k8 * 8);
            f0 = p[0]; f1 = p[1];
        }
        __nv_bfloat162 h0 = __floats2bfloat162_rn(f0.x, f0.y);
        __nv_bfloat162 h1 = __floats2bfloat162_rn(f0.z, f0.w);
        __nv_bfloat162 h2 = __floats2bfloat162_rn(f1.x, f1.y);
        __nv_bfloat162 h3 = __floats2bfloat162_rn(f1.z, f1.w);
        float2 r0 = __bfloat1622float2(h0), r1 = __bfloat1622float2(h1);
        float2 r2 = __bfloat1622float2(h2), r3 = __bfloat1622float2(h3);
        __nv_bfloat162 l0 = __floats2bfloat162_rn(f0.x - r0.x, f0.y - r0.y);
        __nv_bfloat162 l1 = __floats2bfloat162_rn(f0.z - r1.x, f0.w - r1.y);
        __nv_bfloat162 l2 = __floats2bfloat162_rn(f1.x - r2.x, f1.y - r2.y);
        __nv_bfloat162 l3 = __floats2bfloat162_rn(f1.z - r3.x, f1.w - r3.y);
        uint32_t sw = SWZ((uint32_t)(eL * 128 + k8 * 16));
        *(uint4*)(ahi + sw) = make_uint4(bf2u(h0), bf2u(h1), bf2u(h2), bf2u(h3));
        *(uint4*)(alo + sw) = make_uint4(bf2u(l0), bf2u(l1), bf2u(l2), bf2u(l3));
    }
    if (tid < 256) {
        int which = tid >> 7, e = tid & 127;
        int v = 0;
        if (e < nE) v = eidx[which * E + base + e];
        ((int*)(sm + OFF_SIDX))[bb * 256 + tid] = v;
        if (e < nE) {
            unsigned nd = (unsigned)v;
            if (nd < (unsigned)n_nodes) atomicAdd(&g_degree[nd], 1.f);
        }
    }
}

extern "C" __global__ void __launch_bounds__(THREADS, 1)
edge_kernel(const float* __restrict__ edge_attr,
            const float* __restrict__ W,
            const float* __restrict__ b,
            const float* __restrict__ gamma,
            const float* __restrict__ beta,
            const int* __restrict__ eidx,
            float* __restrict__ out,
            int E, int n_nodes)
{
    extern __shared__ __align__(1024) char sm[];
    const uint32_t sb = smem_u32(sm);
    const int tid  = threadIdx.x;
    const int lane = tid & 31;
    const int warp = tid >> 5;        // 0..15
    const int g    = warp >> 1;       // m-group: edges [16g, 16g+16)
    const int h    = warp & 1;        // n-half: channels [64h, 64h+64)
    const int n_tiles = (E + TM - 1) / TM;

    // ---- stage W^T hi/lo (Wt[n][k], 128B rows, SWZ) + bias ----
#pragma unroll
    for (int i = 0; i < 16; i++) {
        int j = tid + THREADS * i;           // j = k*128 + n (coalesced)
        int k = j >> 7, n = j & 127;
        float w = W[j];
        __nv_bfloat16 hi = __float2bfloat16_rn(w);
        __nv_bfloat16 lo = __float2bfloat16_rn(w - __bfloat162float(hi));
        uint32_t sw = SWZ((uint32_t)(n * 128 + k * 2));
        *(__nv_bfloat16*)(sm + OFF_WHI + sw) = hi;
        *(__nv_bfloat16*)(sm + OFF_WLO + sw) = lo;
    }
    if (tid < NDIM) ((float*)(sm + OFF_BIAS))[tid] = b[tid];

    const float4 g4  = ((const float4*)gamma)[lane];
    const float4 bt4 = ((const float4*)beta)[lane];
    const float* smbias = (const float*)(sm + OFF_BIAS);
    float* shp = (float*)(sm + OFF_SH);
    float2* spart = (float2*)(sm + OFF_SPART);

    stage_tile(sm, edge_attr, eidx, blockIdx.x, 0, E, n_tiles, n_nodes, tid);
    __syncthreads();

    int pb = 0;
    for (int mt = blockIdx.x; mt < n_tiles; mt += gridDim.x) {
        const int nE_cur = min(TM, E - mt * TM);

        // ====== GEMM: warp (g,h) -> edges [16g,16g+16) x ch [64h,64h+64) =====
        float cfr[8][4];
#pragma unroll
        for (int nb = 0; nb < 8; nb++) {
            cfr[nb][0] = 0.f; cfr[nb][1] = 0.f; cfr[nb][2] = 0.f; cfr[nb][3] = 0.f;
        }
        const uint32_t abase = sb + OFF_A + pb * ABUF;
        const int arow = g * 16 + (lane & 15);
#pragma unroll
        for (int ks = 0; ks < 4; ks++) {
            uint32_t ahi[4], alo[4];
            {
                uint32_t byte = (uint32_t)(arow * 128 + (ks * 2 + (lane >> 4)) * 16);
                uint32_t ad = abase + SWZ(byte);
                LDMX4(ahi, ad);
                LDMX4(alo, ad + APART);
            }
#pragma unroll
            for (int nb2 = 0; nb2 < 4; nb2++) {
                uint32_t bh[4], bl[4];
                int nrow = h * 64 + nb2 * 16 + ((lane >> 4) << 3) + (lane & 7);
                int kc   = ks * 2 + ((lane >> 3) & 1);
                uint32_t byte = (uint32_t)(nrow * 128 + kc * 16);
                uint32_t bd = sb + OFF_WHI + SWZ(byte);
                LDMX4(bh, bd);
                LDMX4(bl, bd + 16384);
                MMA16816(cfr[2 * nb2],     ahi, bh[0], bh[1]);   // hi*hi
                MMA16816(cfr[2 * nb2],     ahi, bl[0], bl[1]);   // hi*lo
                MMA16816(cfr[2 * nb2],     alo, bh[0], bh[1]);   // lo*hi
                MMA16816(cfr[2 * nb2 + 1], ahi, bh[2], bh[3]);
                MMA16816(cfr[2 * nb2 + 1], ahi, bl[2], bl[3]);
                MMA16816(cfr[2 * nb2 + 1], alo, bh[2], bh[3]);
            }
        }

        // ====== epilogue: bias+relu, partial sums (64 ch per warp) ===========
        const int colbase = (lane & 3) * 2;
        float s_a = 0.f, s2_a = 0.f, s_b = 0.f, s2_b = 0.f;
#pragma unroll
        for (int nb = 0; nb < 8; nb++) {
            float2 bb = *(const float2*)(smbias + h * 64 + nb * 8 + colbase);
            float h0 = fmaxf(cfr[nb][0] + bb.x, 0.f);
            float h1 = fmaxf(cfr[nb][1] + bb.y, 0.f);
            float h2 = fmaxf(cfr[nb][2] + bb.x, 0.f);
            float h3 = fmaxf(cfr[nb][3] + bb.y, 0.f);
            cfr[nb][0] = h0; cfr[nb][1] = h1; cfr[nb][2] = h2; cfr[nb][3] = h3;
            s_a += h0 + h1; s2_a += h0 * h0 + h1 * h1;
            s_b += h2 + h3; s2_b += h2 * h2 + h3 * h3;
        }
#pragma unroll
        for (int o = 1; o <= 2; o <<= 1) {      // quad reduction: per-row halves
            s_a  += __shfl_xor_sync(0xFFFFFFFFu, s_a,  o);
            s2_a += __shfl_xor_sync(0xFFFFFFFFu, s2_a, o);
            s_b  += __shfl_xor_sync(0xFFFFFFFFu, s_b,  o);
            s2_b += __shfl_xor_sync(0xFFFFFFFFu, s2_b, o);
        }
        const int ra = g * 16 + (lane >> 2);
        const int rb = ra + 8;
        if ((lane & 3) == 0) {
            spart[ra * 2 + h] = make_float2(s_a, s2_a);
            spart[rb * 2 + h] = make_float2(s_b, s2_b);
        }
        // pair barrier: warps 2g and 2g+1 (64 threads), ids 1..8
        asm volatile("bar.sync %0, 64;" :: "r"(1 + g) : "memory");
        float2 oa = spart[ra * 2 + (h ^ 1)];
        float2 ob = spart[rb * 2 + (h ^ 1)];
        float mu_a  = (s_a + oa.x) * (1.f / NDIM);
        float var_a = (s2_a + oa.y) * (1.f / NDIM) - mu_a * mu_a;
        float rin_a = rsqrtf(var_a + LN_EPS);
        float mu_b  = (s_b + ob.x) * (1.f / NDIM);
        float var_b = (s2_b + ob.y) * (1.f / NDIM) - mu_b * mu_b;
        float rin_b = rsqrtf(var_b + LN_EPS);

        // normalized -> sh (swizzled float2 cols; 64 float2 per row)
        float* rowa = shp + ra * NDIM;
        float* rowb = shp + rb * NDIM;
        const int xa = (ra & 7) << 3, xb = (rb & 7) << 3;
#pragma unroll
        for (int nb = 0; nb < 8; nb++) {
            int j = h * 32 + nb * 4 + (lane & 3);
            float2 va = make_float2((cfr[nb][0] - mu_a) * rin_a,
                                    (cfr[nb][1] - mu_a) * rin_a);
            float2 vb = make_float2((cfr[nb][2] - mu_b) * rin_b,
                                    (cfr[nb][3] - mu_b) * rin_b);
            *(float2*)(rowa + 2 * (j ^ xa)) = va;
            *(float2*)(rowb + 2 * (j ^ xb)) = vb;
        }
        __syncthreads();                       // (B) sh complete

        // ====== scatter: 256 endpoint rows, 16 per warp ======================
        const int* sid = (const int*)(sm + OFF_SIDX) + pb * 256;
#pragma unroll 4
        for (int i = 0; i < 16; i++) {
            int glob = warp * 16 + i;
            int e = glob & 127;
            if (e < nE_cur) {
                unsigned node = (unsigned)sid[glob];
                if (node < (unsigned)n_nodes) {
                    float4 v = ((float4*)(shp + e * NDIM))[lane ^ ((e & 7) << 2)];
                    float4 vv;
                    vv.x = v.x * g4.x + bt4.x;
                    vv.y = v.y * g4.y + bt4.y;
                    vv.z = v.z * g4.z + bt4.z;
                    vv.w = v.w * g4.w + bt4.w;
                    RED4(out + (long long)node * NDIM + 4 * lane, vv);
                }
            }
        }

        // stage next tile into the other buffer (no race: different buffers)
        stage_tile(sm, edge_attr, eidx, mt + gridDim.x, pb ^ 1, E, n_tiles,
                   n_nodes, tid);
        __syncthreads();                       // (C) flip
        pb ^= 1;
    }
}

__global__ void finalize_kernel(float4* __restrict__ out, int n_nodes) {
    const int total = n_nodes * (NDIM / 4);
    int i = blockIdx.x * blockDim.x + threadIdx.x;
    int stride = gridDim.x * blockDim.x;
    for (int j = i; j < total; j += stride) {
        int node = j >> 5;
        float d = fmaxf(g_degree[node], 1.f);
        float inv = 1.f / d;
        float4 v = out[j];
        v.x *= inv; v.y *= inv; v.z *= inv; v.w *= inv;
        out[j] = v;
    }
}

extern "C" void kernel_launch(void* const* d_in, const int* in_sizes, int n_in,
                              void* d_out, int out_size) {
    // ---- resolve inputs by element count (order-permutation-proof) ----
    int ia = 0;
    for (int i = 1; i < n_in; i++)
        if (in_sizes[i] > in_sizes[ia]) ia = i;
    const float* edge_attr = (const float*)d_in[ia];
    const int E = in_sizes[ia] / EDIM;

    const float *W = 0, *b = 0, *gma = 0, *bta = 0;
    const int* eidx = 0;
    for (int i = 0; i < n_in; i++) {
        if (i == ia) continue;
        int s = in_sizes[i];
        if (s == EDIM * NDIM)      W = (const float*)d_in[i];
        else if (s == 2 * E)       eidx = (const int*)d_in[i];
        else if (s == NDIM) {
            if (!b)        b   = (const float*)d_in[i];
            else if (!gma) gma = (const float*)d_in[i];
            else           bta = (const float*)d_in[i];
        }
    }
    float* out = (float*)d_out;
    int n_nodes = out_size / NDIM;
    if (n_nodes > MAXNODES) n_nodes = MAXNODES;

    zero_kernel<<<2048, 256>>>((float4*)out, out_size / 4, n_nodes);

    // two noops: ncu capture profiles launch index 3 -> edge_kernel
    noop_kernel<<<1, 32>>>();
    noop_kernel<<<1, 32>>>();

    static int smem_set = 0;
    if (!smem_set) {
        cudaFuncSetAttribute(edge_kernel,
                             cudaFuncAttributeMaxDynamicSharedMemorySize, SMEM_TOTAL);
        smem_set = 1;
    }
    edge_kernel<<<148, THREADS, SMEM_TOTAL>>>(edge_attr, W, b, gma, bta, eidx,
                                              out, E, n_nodes);

    finalize_kernel<<<1024, 256>>>((float4*)out, n_nodes);
}

// round 12
// speedup vs baseline: 1.0623x; 1.0623x over previous
#include <cuda_runtime.h>
#include <cuda_bf16.h>
#include <cstdint>

#define EDIM 64
#define NDIM 128
#define TM   64             // edges per tile
#define THREADS 256
#define MAXNODES 65536
#define LN_EPS 1e-5f

// ---- dynamic smem layout (bytes) ----
#define OFF_WHI   0         // W^T hi: 128 n-rows x 128B
#define OFF_WLO   16384
#define OFF_A     32768     // conv A: 2 bufs x (hi 8192 + lo 8192)
#define ACONV     16384
#define APART     8192
#define OFF_RAW   65536     // raw fp32 tiles: 2 x 16384
#define RAWBUF    16384
#define OFF_BIAS  98304     // float[128]
#define OFF_GAM   98816
#define OFF_BET   99328
#define OFF_SPART 99840     // float2[64][2]
#define SMEM_TOTAL 100864

#define SWZ(x) ((x) ^ (((x) >> 3) & 0x70))

#define LDMX4(r, addr) \
    asm volatile("ldmatrix.sync.aligned.m8n8.x4.shared.b16 {%0,%1,%2,%3}, [%4];" \
        : "=r"((r)[0]), "=r"((r)[1]), "=r"((r)[2]), "=r"((r)[3]) : "r"(addr))

#define MMA16816(c, a, b0, b1) \
    asm volatile("mma.sync.aligned.m16n8k16.row.col.f32.bf16.bf16.f32 " \
        "{%0,%1,%2,%3}, {%4,%5,%6,%7}, {%8,%9}, {%0,%1,%2,%3};" \
        : "+f"((c)[0]), "+f"((c)[1]), "+f"((c)[2]), "+f"((c)[3]) \
        : "r"((a)[0]), "r"((a)[1]), "r"((a)[2]), "r"((a)[3]), "r"(b0), "r"(b1))

#define RED2(ptr, x, y) \
    asm volatile("red.global.add.v2.f32 [%0], {%1,%2};" \
                 :: "l"(ptr), "f"(x), "f"(y) : "memory")

#define CPASYNC16(dst, src) \
    asm volatile("cp.async.cg.shared.global [%0], [%1], 16;" \
                 :: "r"(dst), "l"(src) : "memory")
#define CP_COMMIT()  asm volatile("cp.async.commit_group;" ::: "memory")
#define CP_WAIT0()   asm volatile("cp.async.wait_group 0;" ::: "memory")

__device__ __forceinline__ uint32_t smem_u32(const void* p) {
    uint32_t a;
    asm("{ .reg .u64 t; cvta.to.shared.u64 t, %1; cvt.u32.u64 %0, t; }" : "=r"(a) : "l"(p));
    return a;
}
__device__ __forceinline__ uint32_t bf2u(__nv_bfloat162 h) {
    return *reinterpret_cast<uint32_t*>(&h);
}

__device__ float g_degree[MAXNODES];

__global__ void zero_kernel(float4* __restrict__ out, int n_out4, int n_nodes) {
    int i = blockIdx.x * blockDim.x + threadIdx.x;
    int stride = gridDim.x * blockDim.x;
    float4 z = make_float4(0.f, 0.f, 0.f, 0.f);
    for (int j = i; j < n_out4; j += stride) out[j] = z;
    for (int j = i; j < n_nodes; j += stride) g_degree[j] = 0.f;
}
__global__ void noop_kernel() {}

// issue cp.async of raw fp32 tile tt into raw buffer `buf` (zero-fill tails)
__device__ __forceinline__ void issue_cp(
    char* sm, uint32_t sb, const float* __restrict__ edge_attr,
    int tt, int buf, int E, int n_tiles, int tid)
{
    if (tt >= n_tiles) return;
    const int base = tt * TM;
    const uint32_t dbase = sb + OFF_RAW + buf * RAWBUF;
#pragma unroll
    for (int i = 0; i < 4; i++) {
        int idx = tid + THREADS * i;          // 0..1023 float4 slots (16/edge)
        int e = idx >> 4, k4 = idx & 15;
        if (base + e < E) {
            CPASYNC16(dbase + idx * 16,
                      edge_attr + (long long)(base + e) * EDIM + k4 * 4);
        } else {
            *(uint4*)(sm + OFF_RAW + buf * RAWBUF + idx * 16) =
                make_uint4(0u, 0u, 0u, 0u);
        }
    }
    CP_COMMIT();
}

// convert raw fp32 tile -> hi/lo bf16 (SWZ layout) in conv buffer `buf`
__device__ __forceinline__ void convert_tile(char* sm, int buf, int tid) {
    const float* raw = (const float*)(sm + OFF_RAW + buf * RAWBUF);
    char* chi = sm + OFF_A + buf * ACONV;
#pragma unroll
    for (int i = 0; i < 2; i++) {
        int c = tid + THREADS * i;            // 0..511 chunks of 8 floats
        int e = c >> 3, k8 = c & 7;
        const float4* p = (const float4*)(raw + e * EDIM + k8 * 8);
        float4 f0 = p[0], f1 = p[1];
        __nv_bfloat162 h0 = __floats2bfloat162_rn(f0.x, f0.y);
        __nv_bfloat162 h1 = __floats2bfloat162_rn(f0.z, f0.w);
        __nv_bfloat162 h2 = __floats2bfloat162_rn(f1.x, f1.y);
        __nv_bfloat162 h3 = __floats2bfloat162_rn(f1.z, f1.w);
        float2 r0 = __bfloat1622float2(h0), r1 = __bfloat1622float2(h1);
        float2 r2 = __bfloat1622float2(h2), r3 = __bfloat1622float2(h3);
        __nv_bfloat162 l0 = __floats2bfloat162_rn(f0.x - r0.x, f0.y - r0.y);
        __nv_bfloat162 l1 = __floats2bfloat162_rn(f0.z - r1.x, f0.w - r1.y);
        __nv_bfloat162 l2 = __floats2bfloat162_rn(f1.x - r2.x, f1.y - r2.y);
        __nv_bfloat162 l3 = __floats2bfloat162_rn(f1.z - r3.x, f1.w - r3.y);
        uint32_t sw = SWZ((uint32_t)(e * 128 + k8 * 16));
        *(uint4*)(chi + sw) = make_uint4(bf2u(h0), bf2u(h1), bf2u(h2), bf2u(h3));
        *(uint4*)(chi + APART + sw) = make_uint4(bf2u(l0), bf2u(l1), bf2u(l2), bf2u(l3));
    }
}

extern "C" __global__ void __launch_bounds__(THREADS, 2)
edge_kernel(const float* __restrict__ edge_attr,
            const float* __restrict__ W,
            const float* __restrict__ b,
            const float* __restrict__ gamma,
            const float* __restrict__ beta,
            const int* __restrict__ eidx,
            float* __restrict__ out,
            int E, int n_nodes)
{
    extern __shared__ __align__(1024) char sm[];
    const uint32_t sb = smem_u32(sm);
    const int tid  = threadIdx.x;
    const int lane = tid & 31;
    const int warp = tid >> 5;        // 0..7
    const int g    = warp >> 1;       // m-group: edges [16g, 16g+16)
    const int h    = warp & 1;        // n-half: channels [64h, 64h+64)
    const int n_tiles = (E + TM - 1) / TM;

    // ---- stage W^T hi/lo + bias/gamma/beta ----
#pragma unroll
    for (int i = 0; i < 32; i++) {
        int j = tid + THREADS * i;           // j = k*128 + n (coalesced)
        int k = j >> 7, n = j & 127;
        float w = W[j];
        __nv_bfloat16 hi = __float2bfloat16_rn(w);
        __nv_bfloat16 lo = __float2bfloat16_rn(w - __bfloat162float(hi));
        uint32_t sw = SWZ((uint32_t)(n * 128 + k * 2));
        *(__nv_bfloat16*)(sm + OFF_WHI + sw) = hi;
        *(__nv_bfloat16*)(sm + OFF_WLO + sw) = lo;
    }
    if (tid < NDIM) {
        ((float*)(sm + OFF_BIAS))[tid] = b[tid];
        ((float*)(sm + OFF_GAM))[tid]  = gamma[tid];
        ((float*)(sm + OFF_BET))[tid]  = beta[tid];
    }

    const float* smbias = (const float*)(sm + OFF_BIAS);
    const float* smgam  = (const float*)(sm + OFF_GAM);
    const float* smbet  = (const float*)(sm + OFF_BET);
    float2* spart = (float2*)(sm + OFF_SPART);

    // ---- pipeline prologue ----
    const int t0 = blockIdx.x;
    issue_cp(sm, sb, edge_attr, t0, 0, E, n_tiles, tid);
    CP_WAIT0();
    __syncthreads();                  // raw0 + W visible
    convert_tile(sm, 0, tid);
    issue_cp(sm, sb, edge_attr, t0 + gridDim.x, 1, E, n_tiles, tid);
    __syncthreads();                  // conv0 visible

    const int colbase = (lane & 3) * 2;
    int pb = 0;
    for (int mt = t0; mt < n_tiles; mt += gridDim.x) {
        // ---- endpoint indices for this warp's 16 edges (1 LDG lane-wide) ----
        int v = -1;
        {
            int ge = mt * TM + g * 16 + (lane & 15);
            int which = lane >> 4;
            if (ge < E) v = eidx[which * E + ge];
            // degree: count each endpoint ONCE (h==0 warp only; h==1 warp
            // loads v purely for the feature scatter)
            if (h == 0 && (unsigned)v < (unsigned)n_nodes)
                atomicAdd(&g_degree[(unsigned)v], 1.f);
        }

        // ====== GEMM: warp (g,h) -> edges [16g,16g+16) x ch [64h,64h+64) =====
        float cfr[8][4];
#pragma unroll
        for (int nb = 0; nb < 8; nb++) {
            cfr[nb][0] = 0.f; cfr[nb][1] = 0.f; cfr[nb][2] = 0.f; cfr[nb][3] = 0.f;
        }
        const uint32_t abase = sb + OFF_A + pb * ACONV;
        const int arow = g * 16 + (lane & 15);
#pragma unroll
        for (int ks = 0; ks < 4; ks++) {
            uint32_t ahi[4], alo[4];
            {
                uint32_t byte = (uint32_t)(arow * 128 + (ks * 2 + (lane >> 4)) * 16);
                uint32_t ad = abase + SWZ(byte);
                LDMX4(ahi, ad);
                LDMX4(alo, ad + APART);
            }
#pragma unroll
            for (int nb2 = 0; nb2 < 4; nb2++) {
                uint32_t bh[4], bl[4];
                int nrow = h * 64 + nb2 * 16 + ((lane >> 4) << 3) + (lane & 7);
                int kc   = ks * 2 + ((lane >> 3) & 1);
                uint32_t byte = (uint32_t)(nrow * 128 + kc * 16);
                uint32_t bd = sb + OFF_WHI + SWZ(byte);
                LDMX4(bh, bd);
                LDMX4(bl, bd + 16384);
                MMA16816(cfr[2 * nb2],     ahi, bh[0], bh[1]);   // hi*hi
                MMA16816(cfr[2 * nb2],     ahi, bl[0], bl[1]);   // hi*lo
                MMA16816(cfr[2 * nb2],     alo, bh[0], bh[1]);   // lo*hi
                MMA16816(cfr[2 * nb2 + 1], ahi, bh[2], bh[3]);
                MMA16816(cfr[2 * nb2 + 1], ahi, bl[2], bl[3]);
                MMA16816(cfr[2 * nb2 + 1], alo, bh[2], bh[3]);
            }
        }

        // ====== bias + relu + per-row partial sums ======
        float s_a = 0.f, s2_a = 0.f, s_b = 0.f, s2_b = 0.f;
#pragma unroll
        for (int nb = 0; nb < 8; nb++) {
            float2 bb = *(const float2*)(smbias + h * 64 + nb * 8 + colbase);
            float h0 = fmaxf(cfr[nb][0] + bb.x, 0.f);
            float h1 = fmaxf(cfr[nb][1] + bb.y, 0.f);
            float h2 = fmaxf(cfr[nb][2] + bb.x, 0.f);
            float h3 = fmaxf(cfr[nb][3] + bb.y, 0.f);
            cfr[nb][0] = h0; cfr[nb][1] = h1; cfr[nb][2] = h2; cfr[nb][3] = h3;
            s_a += h0 + h1; s2_a += h0 * h0 + h1 * h1;
            s_b += h2 + h3; s2_b += h2 * h2 + h3 * h3;
        }
#pragma unroll
        for (int o = 1; o <= 2; o <<= 1) {
            s_a  += __shfl_xor_sync(0xFFFFFFFFu, s_a,  o);
            s2_a += __shfl_xor_sync(0xFFFFFFFFu, s2_a, o);
            s_b  += __shfl_xor_sync(0xFFFFFFFFu, s_b,  o);
            s2_b += __shfl_xor_sync(0xFFFFFFFFu, s2_b, o);
        }
        const int ra = g * 16 + (lane >> 2);
        const int rb = ra + 8;
        if ((lane & 3) == 0) {
            spart[ra * 2 + h] = make_float2(s_a, s2_a);
            spart[rb * 2 + h] = make_float2(s_b, s2_b);
        }
        asm volatile("bar.sync %0, 64;" :: "r"(1 + g) : "memory");
        float2 oa = spart[ra * 2 + (h ^ 1)];
        float2 ob = spart[rb * 2 + (h ^ 1)];
        float mu_a  = (s_a + oa.x) * (1.f / NDIM);
        float var_a = (s2_a + oa.y) * (1.f / NDIM) - mu_a * mu_a;
        float rin_a = rsqrtf(var_a + LN_EPS);
        float mu_b  = (s_b + ob.x) * (1.f / NDIM);
        float var_b = (s2_b + ob.y) * (1.f / NDIM) - mu_b * mu_b;
        float rin_b = rsqrtf(var_b + LN_EPS);

        // ====== scatter straight from fragments (red.v2, no transpose) ======
        int na0 = __shfl_sync(0xFFFFFFFFu, v, lane >> 2);
        int nb0 = __shfl_sync(0xFFFFFFFFu, v, 8 + (lane >> 2));
        int na1 = __shfl_sync(0xFFFFFFFFu, v, 16 + (lane >> 2));
        int nb1 = __shfl_sync(0xFFFFFFFFu, v, 24 + (lane >> 2));
        const bool va0 = (unsigned)na0 < (unsigned)n_nodes;
        const bool va1 = (unsigned)na1 < (unsigned)n_nodes;
        const bool vb0 = (unsigned)nb0 < (unsigned)n_nodes;
        const bool vb1 = (unsigned)nb1 < (unsigned)n_nodes;
        float* pa0 = out + (long long)na0 * NDIM;
        float* pa1 = out + (long long)na1 * NDIM;
        float* pb0 = out + (long long)nb0 * NDIM;
        float* pb1 = out + (long long)nb1 * NDIM;
#pragma unroll
        for (int nb = 0; nb < 8; nb++) {
            int ch = h * 64 + nb * 8 + colbase;
            float2 gg = *(const float2*)(smgam + ch);
            float2 be = *(const float2*)(smbet + ch);
            float ax = (cfr[nb][0] - mu_a) * rin_a * gg.x + be.x;
            float ay = (cfr[nb][1] - mu_a) * rin_a * gg.y + be.y;
            float bx = (cfr[nb][2] - mu_b) * rin_b * gg.x + be.x;
            float by = (cfr[nb][3] - mu_b) * rin_b * gg.y + be.y;
            if (va0) RED2(pa0 + ch, ax, ay);
            if (va1) RED2(pa1 + ch, ax, ay);
            if (vb0) RED2(pb0 + ch, bx, by);
            if (vb1) RED2(pb1 + ch, bx, by);
        }

        // ====== pipeline advance ======
        CP_WAIT0();
        __syncthreads();                   // raw[pb^1] landed; conv[pb] free
        convert_tile(sm, pb ^ 1, tid);
        issue_cp(sm, sb, edge_attr, mt + 2 * gridDim.x, pb, E, n_tiles, tid);
        __syncthreads();                   // conv[pb^1] visible
        pb ^= 1;
    }
}

__global__ void finalize_kernel(float4* __restrict__ out, int n_nodes) {
    const int total = n_nodes * (NDIM / 4);
    int i = blockIdx.x * blockDim.x + threadIdx.x;
    int stride = gridDim.x * blockDim.x;
    for (int j = i; j < total; j += stride) {
        int node = j >> 5;
        float d = fmaxf(g_degree[node], 1.f);
        float inv = 1.f / d;
        float4 v = out[j];
        v.x *= inv; v.y *= inv; v.z *= inv; v.w *= inv;
        out[j] = v;
    }
}

extern "C" void kernel_launch(void* const* d_in, const int* in_sizes, int n_in,
                              void* d_out, int out_size) {
    // ---- resolve inputs by element count (order-permutation-proof) ----
    int ia = 0;
    for (int i = 1; i < n_in; i++)
        if (in_sizes[i] > in_sizes[ia]) ia = i;
    const float* edge_attr = (const float*)d_in[ia];
    const int E = in_sizes[ia] / EDIM;

    const float *W = 0, *b = 0, *gma = 0, *bta = 0;
    const int* eidx = 0;
    for (int i = 0; i < n_in; i++) {
        if (i == ia) continue;
        int s = in_sizes[i];
        if (s == EDIM * NDIM)      W = (const float*)d_in[i];
        else if (s == 2 * E)       eidx = (const int*)d_in[i];
        else if (s == NDIM) {
            if (!b)        b   = (const float*)d_in[i];
            else if (!gma) gma = (const float*)d_in[i];
            else           bta = (const float*)d_in[i];
        }
    }
    float* out = (float*)d_out;
    int n_nodes = out_size / NDIM;
    if (n_nodes > MAXNODES) n_nodes = MAXNODES;

    zero_kernel<<<2048, 256>>>((float4*)out, out_size / 4, n_nodes);

    // two noops: ncu capture profiles launch index 3 -> edge_kernel
    noop_kernel<<<1, 32>>>();
    noop_kernel<<<1, 32>>>();

    static int smem_set = 0;
    if (!smem_set) {
        cudaFuncSetAttribute(edge_kernel,
                             cudaFuncAttributeMaxDynamicSharedMemorySize, SMEM_TOTAL);
        smem_set = 1;
    }
    const int n_tiles = (E + TM - 1) / TM;
    int grid = 2 * 148;
    if (grid > n_tiles) grid = n_tiles;
    edge_kernel<<<grid, THREADS, SMEM_TOTAL>>>(edge_attr, W, b, gma, bta, eidx,
                                               out, E, n_nodes);

    finalize_kernel<<<1024, 256>>>((float4*)out, n_nodes);
}

// round 13
// speedup vs baseline: 1.2789x; 1.2039x over previous
#include <cuda_runtime.h>
#include <cuda_bf16.h>
#include <cstdint>

#define EDIM 64
#define NDIM 128
#define TM   64             // edges per tile
#define THREADS 256
#define MAXNODES 65536
#define LN_EPS 1e-5f

// ---- dynamic smem layout (bytes) ----
#define OFF_WHI   0         // W^T hi: 128 n-rows x 128B
#define OFF_WLO   16384
#define OFF_CONV  32768     // conv A (single buf): hi 8192 + lo 8192
#define APART     8192
#define OFF_RAW   49152     // raw fp32 tile: 16384
#define OFF_SH    65536     // float[64][128] normalized rows (swizzled)
#define OFF_SIDX  98304     // int[128]
#define OFF_BIAS  98816     // float[128]
#define OFF_SPART 99328     // float2[64][2]
#define SMEM_TOTAL 100352

#define SWZ(x) ((x) ^ (((x) >> 3) & 0x70))

#define LDMX4(r, addr) \
    asm volatile("ldmatrix.sync.aligned.m8n8.x4.shared.b16 {%0,%1,%2,%3}, [%4];" \
        : "=r"((r)[0]), "=r"((r)[1]), "=r"((r)[2]), "=r"((r)[3]) : "r"(addr))

#define MMA16816(c, a, b0, b1) \
    asm volatile("mma.sync.aligned.m16n8k16.row.col.f32.bf16.bf16.f32 " \
        "{%0,%1,%2,%3}, {%4,%5,%6,%7}, {%8,%9}, {%0,%1,%2,%3};" \
        : "+f"((c)[0]), "+f"((c)[1]), "+f"((c)[2]), "+f"((c)[3]) \
        : "r"((a)[0]), "r"((a)[1]), "r"((a)[2]), "r"((a)[3]), "r"(b0), "r"(b1))

#define RED4(ptr, v) \
    asm volatile("red.global.add.v4.f32 [%0], {%1,%2,%3,%4};" \
                 :: "l"(ptr), "f"((v).x), "f"((v).y), "f"((v).z), "f"((v).w) : "memory")

#define CPASYNC16(dst, src) \
    asm volatile("cp.async.cg.shared.global [%0], [%1], 16;" \
                 :: "r"(dst), "l"(src) : "memory")
#define CP_COMMIT()  asm volatile("cp.async.commit_group;" ::: "memory")
#define CP_WAIT0()   asm volatile("cp.async.wait_group 0;" ::: "memory")

__device__ __forceinline__ uint32_t smem_u32(const void* p) {
    uint32_t a;
    asm("{ .reg .u64 t; cvta.to.shared.u64 t, %1; cvt.u32.u64 %0, t; }" : "=r"(a) : "l"(p));
    return a;
}
__device__ __forceinline__ uint32_t bf2u(__nv_bfloat162 h) {
    return *reinterpret_cast<uint32_t*>(&h);
}

__device__ float g_degree[MAXNODES];

__global__ void zero_kernel(float4* __restrict__ out, int n_out4, int n_nodes) {
    int i = blockIdx.x * blockDim.x + threadIdx.x;
    int stride = gridDim.x * blockDim.x;
    float4 z = make_float4(0.f, 0.f, 0.f, 0.f);
    for (int j = i; j < n_out4; j += stride) out[j] = z;
    for (int j = i; j < n_nodes; j += stride) g_degree[j] = 0.f;
}
__global__ void noop_kernel() {}

// issue cp.async of raw fp32 tile tt (zero-fill tails)
__device__ __forceinline__ void issue_cp(
    char* sm, uint32_t sb, const float* __restrict__ edge_attr,
    int tt, int E, int n_tiles, int tid)
{
    if (tt >= n_tiles) return;
    const int base = tt * TM;
#pragma unroll
    for (int i = 0; i < 4; i++) {
        int idx = tid + THREADS * i;          // 0..1023 float4 slots (16/edge)
        int e = idx >> 4, k4 = idx & 15;
        if (base + e < E) {
            CPASYNC16(sb + OFF_RAW + idx * 16,
                      edge_attr + (long long)(base + e) * EDIM + k4 * 4);
        } else {
            *(uint4*)(sm + OFF_RAW + idx * 16) = make_uint4(0u, 0u, 0u, 0u);
        }
    }
    CP_COMMIT();
}

// convert raw fp32 tile -> hi/lo bf16 (SWZ layout) in conv buffer
__device__ __forceinline__ void convert_tile(char* sm, int tid) {
    const float* raw = (const float*)(sm + OFF_RAW);
    char* chi = sm + OFF_CONV;
#pragma unroll
    for (int i = 0; i < 2; i++) {
        int c = tid + THREADS * i;            // 0..511 chunks of 8 floats
        int e = c >> 3, k8 = c & 7;
        const float4* p = (const float4*)(raw + e * EDIM + k8 * 8);
        float4 f0 = p[0], f1 = p[1];
        __nv_bfloat162 h0 = __floats2bfloat162_rn(f0.x, f0.y);
        __nv_bfloat162 h1 = __floats2bfloat162_rn(f0.z, f0.w);
        __nv_bfloat162 h2 = __floats2bfloat162_rn(f1.x, f1.y);
        __nv_bfloat162 h3 = __floats2bfloat162_rn(f1.z, f1.w);
        float2 r0 = __bfloat1622float2(h0), r1 = __bfloat1622float2(h1);
        float2 r2 = __bfloat1622float2(h2), r3 = __bfloat1622float2(h3);
        __nv_bfloat162 l0 = __floats2bfloat162_rn(f0.x - r0.x, f0.y - r0.y);
        __nv_bfloat162 l1 = __floats2bfloat162_rn(f0.z - r1.x, f0.w - r1.y);
        __nv_bfloat162 l2 = __floats2bfloat162_rn(f1.x - r2.x, f1.y - r2.y);
        __nv_bfloat162 l3 = __floats2bfloat162_rn(f1.z - r3.x, f1.w - r3.y);
        uint32_t sw = SWZ((uint32_t)(e * 128 + k8 * 16));
        *(uint4*)(chi + sw) = make_uint4(bf2u(h0), bf2u(h1), bf2u(h2), bf2u(h3));
        *(uint4*)(chi + APART + sw) = make_uint4(bf2u(l0), bf2u(l1), bf2u(l2), bf2u(l3));
    }
}

extern "C" __global__ void __launch_bounds__(THREADS, 2)
edge_kernel(const float* __restrict__ edge_attr,
            const float* __restrict__ W,
            const float* __restrict__ b,
            const float* __restrict__ gamma,
            const float* __restrict__ beta,
            const int* __restrict__ eidx,
            float* __restrict__ out,
            int E, int n_nodes)
{
    extern __shared__ __align__(1024) char sm[];
    const uint32_t sb = smem_u32(sm);
    const int tid  = threadIdx.x;
    const int lane = tid & 31;
    const int warp = tid >> 5;        // 0..7
    const int g    = warp >> 1;       // m-group: edges [16g, 16g+16)
    const int h    = warp & 1;        // n-half: channels [64h, 64h+64)
    const int n_tiles = (E + TM - 1) / TM;

    // ---- pipeline prologue: first raw tile in flight during W staging ----
    issue_cp(sm, sb, edge_attr, blockIdx.x, E, n_tiles, tid);

    // ---- stage W^T hi/lo + bias ----
#pragma unroll
    for (int i = 0; i < 32; i++) {
        int j = tid + THREADS * i;           // j = k*128 + n (coalesced)
        int k = j >> 7, n = j & 127;
        float w = W[j];
        __nv_bfloat16 hi = __float2bfloat16_rn(w);
        __nv_bfloat16 lo = __float2bfloat16_rn(w - __bfloat162float(hi));
        uint32_t sw = SWZ((uint32_t)(n * 128 + k * 2));
        *(__nv_bfloat16*)(sm + OFF_WHI + sw) = hi;
        *(__nv_bfloat16*)(sm + OFF_WLO + sw) = lo;
    }
    if (tid < NDIM) ((float*)(sm + OFF_BIAS))[tid] = b[tid];

    const float4 g4  = ((const float4*)gamma)[lane];
    const float4 bt4 = ((const float4*)beta)[lane];
    const float* smbias = (const float*)(sm + OFF_BIAS);
    float* shp = (float*)(sm + OFF_SH);
    float2* spart = (float2*)(sm + OFF_SPART);
    int* sidx = (int*)(sm + OFF_SIDX);

    CP_WAIT0();
    __syncthreads();                  // raw0 + W visible
    convert_tile(sm, tid);
    __syncthreads();                  // conv visible (raw free)
    issue_cp(sm, sb, edge_attr, blockIdx.x + gridDim.x, E, n_tiles, tid);

    const int colbase = (lane & 3) * 2;
    for (int mt = blockIdx.x; mt < n_tiles; mt += gridDim.x) {
        const int nE_cur = min(TM, E - mt * TM);

        // ---- endpoint indices + degree (one writer per endpoint) ----
        if (tid < 2 * TM) {
            int which = tid >> 6, e = tid & 63;
            int ge = mt * TM + e;
            int v = -1;
            if (ge < E) v = eidx[which * E + ge];
            sidx[tid] = v;
            if ((unsigned)v < (unsigned)n_nodes)
                atomicAdd(&g_degree[(unsigned)v], 1.f);
        }

        // ====== GEMM: warp (g,h) -> edges [16g,16g+16) x ch [64h,64h+64) =====
        float cfr[8][4];
#pragma unroll
        for (int nb = 0; nb < 8; nb++) {
            cfr[nb][0] = 0.f; cfr[nb][1] = 0.f; cfr[nb][2] = 0.f; cfr[nb][3] = 0.f;
        }
        const int arow = g * 16 + (lane & 15);
#pragma unroll
        for (int ks = 0; ks < 4; ks++) {
            uint32_t ahi[4], alo[4];
            {
                uint32_t byte = (uint32_t)(arow * 128 + (ks * 2 + (lane >> 4)) * 16);
                uint32_t ad = sb + OFF_CONV + SWZ(byte);
                LDMX4(ahi, ad);
                LDMX4(alo, ad + APART);
            }
#pragma unroll
            for (int nb2 = 0; nb2 < 4; nb2++) {
                uint32_t bh[4], bl[4];
                int nrow = h * 64 + nb2 * 16 + ((lane >> 4) << 3) + (lane & 7);
                int kc   = ks * 2 + ((lane >> 3) & 1);
                uint32_t byte = (uint32_t)(nrow * 128 + kc * 16);
                uint32_t bd = sb + OFF_WHI + SWZ(byte);
                LDMX4(bh, bd);
                LDMX4(bl, bd + 16384);
                MMA16816(cfr[2 * nb2],     ahi, bh[0], bh[1]);   // hi*hi
                MMA16816(cfr[2 * nb2],     ahi, bl[0], bl[1]);   // hi*lo
                MMA16816(cfr[2 * nb2],     alo, bh[0], bh[1]);   // lo*hi
                MMA16816(cfr[2 * nb2 + 1], ahi, bh[2], bh[3]);
                MMA16816(cfr[2 * nb2 + 1], ahi, bl[2], bl[3]);
                MMA16816(cfr[2 * nb2 + 1], alo, bh[2], bh[3]);
            }
        }

        // ====== bias + relu + per-row partial sums ======
        float s_a = 0.f, s2_a = 0.f, s_b = 0.f, s2_b = 0.f;
#pragma unroll
        for (int nb = 0; nb < 8; nb++) {
            float2 bb = *(const float2*)(smbias + h * 64 + nb * 8 + colbase);
            float h0 = fmaxf(cfr[nb][0] + bb.x, 0.f);
            float h1 = fmaxf(cfr[nb][1] + bb.y, 0.f);
            float h2 = fmaxf(cfr[nb][2] + bb.x, 0.f);
            float h3 = fmaxf(cfr[nb][3] + bb.y, 0.f);
            cfr[nb][0] = h0; cfr[nb][1] = h1; cfr[nb][2] = h2; cfr[nb][3] = h3;
            s_a += h0 + h1; s2_a += h0 * h0 + h1 * h1;
            s_b += h2 + h3; s2_b += h2 * h2 + h3 * h3;
        }
#pragma unroll
        for (int o = 1; o <= 2; o <<= 1) {
            s_a  += __shfl_xor_sync(0xFFFFFFFFu, s_a,  o);
            s2_a += __shfl_xor_sync(0xFFFFFFFFu, s2_a, o);
            s_b  += __shfl_xor_sync(0xFFFFFFFFu, s_b,  o);
            s2_b += __shfl_xor_sync(0xFFFFFFFFu, s2_b, o);
        }
        const int ra = g * 16 + (lane >> 2);
        const int rb = ra + 8;
        if ((lane & 3) == 0) {
            spart[ra * 2 + h] = make_float2(s_a, s2_a);
            spart[rb * 2 + h] = make_float2(s_b, s2_b);
        }
        asm volatile("bar.sync %0, 64;" :: "r"(1 + g) : "memory");
        float2 oa = spart[ra * 2 + (h ^ 1)];
        float2 ob = spart[rb * 2 + (h ^ 1)];
        float mu_a  = (s_a + oa.x) * (1.f / NDIM);
        float var_a = (s2_a + oa.y) * (1.f / NDIM) - mu_a * mu_a;
        float rin_a = rsqrtf(var_a + LN_EPS);
        float mu_b  = (s_b + ob.x) * (1.f / NDIM);
        float var_b = (s2_b + ob.y) * (1.f / NDIM) - mu_b * mu_b;
        float rin_b = rsqrtf(var_b + LN_EPS);

        // normalized -> sh (swizzled float2 cols, R10-proven layout)
        float* rowa = shp + ra * NDIM;
        float* rowb = shp + rb * NDIM;
        const int xa = (ra & 7) << 3, xb = (rb & 7) << 3;
#pragma unroll
        for (int nb = 0; nb < 8; nb++) {
            int j = h * 32 + nb * 4 + (lane & 3);
            float2 va = make_float2((cfr[nb][0] - mu_a) * rin_a,
                                    (cfr[nb][1] - mu_a) * rin_a);
            float2 vb = make_float2((cfr[nb][2] - mu_b) * rin_b,
                                    (cfr[nb][3] - mu_b) * rin_b);
            *(float2*)(rowa + 2 * (j ^ xa)) = va;
            *(float2*)(rowb + 2 * (j ^ xb)) = vb;
        }
        __syncthreads();                       // (A) sh + sidx ready; conv free

        // ====== coalesced scatter: 128 endpoint rows, 16 per warp ============
#pragma unroll 4
        for (int i = 0; i < 16; i++) {
            int glob = warp * 16 + i;
            int e = glob & 63;
            if (e < nE_cur) {
                unsigned node = (unsigned)sidx[glob];
                if (node < (unsigned)n_nodes) {
                    float4 v = ((float4*)(shp + e * NDIM))[lane ^ ((e & 7) << 2)];
                    float4 vv;
                    vv.x = v.x * g4.x + bt4.x;
                    vv.y = v.y * g4.y + bt4.y;
                    vv.z = v.z * g4.z + bt4.z;
                    vv.w = v.w * g4.w + bt4.w;
                    RED4(out + (long long)node * NDIM + 4 * lane, vv);
                }
            }
        }

        // ====== pipeline advance: convert t+1 into conv, launch t+2 ==========
        if (mt + gridDim.x < n_tiles) {
            CP_WAIT0();                         // raw(t+1) landed
            convert_tile(sm, tid);
        }
        __syncthreads();                        // (B) conv/scatter/sh settled
        issue_cp(sm, sb, edge_attr, mt + 2 * gridDim.x, E, n_tiles, tid);
    }
}

__global__ void finalize_kernel(float4* __restrict__ out, int n_nodes) {
    const int total = n_nodes * (NDIM / 4);
    int i = blockIdx.x * blockDim.x + threadIdx.x;
    int stride = gridDim.x * blockDim.x;
    for (int j = i; j < total; j += stride) {
        int node = j >> 5;
        float d = fmaxf(g_degree[node], 1.f);
        float inv = 1.f / d;
        float4 v = out[j];
        v.x *= inv; v.y *= inv; v.z *= inv; v.w *= inv;
        out[j] = v;
    }
}

extern "C" void kernel_launch(void* const* d_in, const int* in_sizes, int n_in,
                              void* d_out, int out_size) {
    // ---- resolve inputs by element count (order-permutation-proof) ----
    int ia = 0;
    for (int i = 1; i < n_in; i++)
        if (in_sizes[i] > in_sizes[ia]) ia = i;
    const float* edge_attr = (const float*)d_in[ia];
    const int E = in_sizes[ia] / EDIM;

    const float *W = 0, *b = 0, *gma = 0, *bta = 0;
    const int* eidx = 0;
    for (int i = 0; i < n_in; i++) {
        if (i == ia) continue;
        int s = in_sizes[i];
        if (s == EDIM * NDIM)      W = (const float*)d_in[i];
        else if (s == 2 * E)       eidx = (const int*)d_in[i];
        else if (s == NDIM) {
            if (!b)        b   = (const float*)d_in[i];
            else if (!gma) gma = (const float*)d_in[i];
            else           bta = (const float*)d_in[i];
        }
    }
    float* out = (float*)d_out;
    int n_nodes = out_size / NDIM;
    if (n_nodes > MAXNODES) n_nodes = MAXNODES;

    zero_kernel<<<2048, 256>>>((float4*)out, out_size / 4, n_nodes);

    // two noops: ncu capture profiles launch index 3 -> edge_kernel
    noop_kernel<<<1, 32>>>();
    noop_kernel<<<1, 32>>>();

    static int smem_set = 0;
    if (!smem_set) {
        cudaFuncSetAttribute(edge_kernel,
                             cudaFuncAttributeMaxDynamicSharedMemorySize, SMEM_TOTAL);
        smem_set = 1;
    }
    const int n_tiles = (E + TM - 1) / TM;
    int grid = 2 * 148;
    if (grid > n_tiles) grid = n_tiles;
    edge_kernel<<<grid, THREADS, SMEM_TOTAL>>>(edge_attr, W, b, gma, bta, eidx,
                                               out, E, n_nodes);

    finalize_kernel<<<1024, 256>>>((float4*)out, n_nodes);
}

// round 14
// speedup vs baseline: 1.5209x; 1.1893x over previous
#include <cuda_runtime.h>
#include <cuda_bf16.h>
#include <cstdint>

#define EDIM 64
#define NDIM 128
#define TM   64             // edges per tile
#define THREADS 256
#define MAXNODES 65536
#define LN_EPS 1e-5f

// ---- dynamic smem layout (bytes) ----
#define OFF_WHI   0         // W^T hi: 128 n-rows x 128B
#define OFF_WLO   16384
#define OFF_CONV  32768     // conv A (single buf): hi 8192 + lo 8192
#define APART     8192
#define OFF_RAW   49152     // raw fp32 tile: 16384
#define OFF_SH    65536     // float[64][128] normalized rows (swizzled)
#define OFF_SIDX  98304     // int[128]
#define OFF_BIAS  98816     // float[128]
#define OFF_SPART 99328     // float2[64][4] = 2048 B
#define SMEM_TOTAL 101376

#define SWZ(x) ((x) ^ (((x) >> 3) & 0x70))

#define LDMX4(r, addr) \
    asm volatile("ldmatrix.sync.aligned.m8n8.x4.shared.b16 {%0,%1,%2,%3}, [%4];" \
        : "=r"((r)[0]), "=r"((r)[1]), "=r"((r)[2]), "=r"((r)[3]) : "r"(addr))

#define MMA16816(c, a, b0, b1) \
    asm volatile("mma.sync.aligned.m16n8k16.row.col.f32.bf16.bf16.f32 " \
        "{%0,%1,%2,%3}, {%4,%5,%6,%7}, {%8,%9}, {%0,%1,%2,%3};" \
        : "+f"((c)[0]), "+f"((c)[1]), "+f"((c)[2]), "+f"((c)[3]) \
        : "r"((a)[0]), "r"((a)[1]), "r"((a)[2]), "r"((a)[3]), "r"(b0), "r"(b1))

#define RED4(ptr, v) \
    asm volatile("red.global.add.v4.f32 [%0], {%1,%2,%3,%4};" \
                 :: "l"(ptr), "f"((v).x), "f"((v).y), "f"((v).z), "f"((v).w) : "memory")

#define CPASYNC16(dst, src) \
    asm volatile("cp.async.cg.shared.global [%0], [%1], 16;" \
                 :: "r"(dst), "l"(src) : "memory")
#define CP_COMMIT()  asm volatile("cp.async.commit_group;" ::: "memory")
#define CP_WAIT0()   asm volatile("cp.async.wait_group 0;" ::: "memory")

__device__ __forceinline__ uint32_t smem_u32(const void* p) {
    uint32_t a;
    asm("{ .reg .u64 t; cvta.to.shared.u64 t, %1; cvt.u32.u64 %0, t; }" : "=r"(a) : "l"(p));
    return a;
}
__device__ __forceinline__ uint32_t bf2u(__nv_bfloat162 h) {
    return *reinterpret_cast<uint32_t*>(&h);
}

__device__ float g_degree[MAXNODES];

__global__ void zero_kernel(float4* __restrict__ out, int n_out4, int n_nodes) {
    int i = blockIdx.x * blockDim.x + threadIdx.x;
    int stride = gridDim.x * blockDim.x;
    float4 z = make_float4(0.f, 0.f, 0.f, 0.f);
    for (int j = i; j < n_out4; j += stride) out[j] = z;
    for (int j = i; j < n_nodes; j += stride) g_degree[j] = 0.f;
}
__global__ void noop_kernel() {}

// issue cp.async of raw fp32 tile tt (zero-fill tails)
__device__ __forceinline__ void issue_cp(
    char* sm, uint32_t sb, const float* __restrict__ edge_attr,
    int tt, int E, int n_tiles, int tid)
{
    if (tt >= n_tiles) return;
    const int base = tt * TM;
#pragma unroll
    for (int i = 0; i < 4; i++) {
        int idx = tid + THREADS * i;          // 0..1023 float4 slots (16/edge)
        int e = idx >> 4, k4 = idx & 15;
        if (base + e < E) {
            CPASYNC16(sb + OFF_RAW + idx * 16,
                      edge_attr + (long long)(base + e) * EDIM + k4 * 4);
        } else {
            *(uint4*)(sm + OFF_RAW + idx * 16) = make_uint4(0u, 0u, 0u, 0u);
        }
    }
    CP_COMMIT();
}

// convert raw fp32 tile -> hi/lo bf16 (SWZ layout) in conv buffer
__device__ __forceinline__ void convert_tile(char* sm, int tid) {
    const float* raw = (const float*)(sm + OFF_RAW);
    char* chi = sm + OFF_CONV;
#pragma unroll
    for (int i = 0; i < 2; i++) {
        int c = tid + THREADS * i;            // 0..511 chunks of 8 floats
        int e = c >> 3, k8 = c & 7;
        const float4* p = (const float4*)(raw + e * EDIM + k8 * 8);
        float4 f0 = p[0], f1 = p[1];
        __nv_bfloat162 h0 = __floats2bfloat162_rn(f0.x, f0.y);
        __nv_bfloat162 h1 = __floats2bfloat162_rn(f0.z, f0.w);
        __nv_bfloat162 h2 = __floats2bfloat162_rn(f1.x, f1.y);
        __nv_bfloat162 h3 = __floats2bfloat162_rn(f1.z, f1.w);
        float2 r0 = __bfloat1622float2(h0), r1 = __bfloat1622float2(h1);
        float2 r2 = __bfloat1622float2(h2), r3 = __bfloat1622float2(h3);
        __nv_bfloat162 l0 = __floats2bfloat162_rn(f0.x - r0.x, f0.y - r0.y);
        __nv_bfloat162 l1 = __floats2bfloat162_rn(f0.z - r1.x, f0.w - r1.y);
        __nv_bfloat162 l2 = __floats2bfloat162_rn(f1.x - r2.x, f1.y - r2.y);
        __nv_bfloat162 l3 = __floats2bfloat162_rn(f1.z - r3.x, f1.w - r3.y);
        uint32_t sw = SWZ((uint32_t)(e * 128 + k8 * 16));
        *(uint4*)(chi + sw) = make_uint4(bf2u(h0), bf2u(h1), bf2u(h2), bf2u(h3));
        *(uint4*)(chi + APART + sw) = make_uint4(bf2u(l0), bf2u(l1), bf2u(l2), bf2u(l3));
    }
}

extern "C" __global__ void __launch_bounds__(THREADS, 2)
edge_kernel(const float* __restrict__ edge_attr,
            const float* __restrict__ W,
            const float* __restrict__ b,
            const float* __restrict__ gamma,
            const float* __restrict__ beta,
            const int* __restrict__ eidx,
            float* __restrict__ out,
            int E, int n_nodes)
{
    extern __shared__ __align__(1024) char sm[];
    const uint32_t sb = smem_u32(sm);
    const int tid  = threadIdx.x;
    const int lane = tid & 31;
    const int warp = tid >> 5;        // 0..7
    const int g    = warp >> 2;       // m-group: edges [32g, 32g+32)
    const int q    = warp & 3;        // n-quarter: channels [32q, 32q+32)
    const int n_tiles = (E + TM - 1) / TM;

    // ---- pipeline prologue: first raw tile in flight during W staging ----
    issue_cp(sm, sb, edge_attr, blockIdx.x, E, n_tiles, tid);

    // ---- stage W^T hi/lo + bias ----
#pragma unroll
    for (int i = 0; i < 32; i++) {
        int j = tid + THREADS * i;           // j = k*128 + n (coalesced)
        int k = j >> 7, n = j & 127;
        float w = W[j];
        __nv_bfloat16 hi = __float2bfloat16_rn(w);
        __nv_bfloat16 lo = __float2bfloat16_rn(w - __bfloat162float(hi));
        uint32_t sw = SWZ((uint32_t)(n * 128 + k * 2));
        *(__nv_bfloat16*)(sm + OFF_WHI + sw) = hi;
        *(__nv_bfloat16*)(sm + OFF_WLO + sw) = lo;
    }
    if (tid < NDIM) ((float*)(sm + OFF_BIAS))[tid] = b[tid];

    const float4 g4  = ((const float4*)gamma)[lane];
    const float4 bt4 = ((const float4*)beta)[lane];
    const float* smbias = (const float*)(sm + OFF_BIAS);
    float* shp = (float*)(sm + OFF_SH);
    float* spartf = (float*)(sm + OFF_SPART);   // float2[64][4] as floats
    int* sidx = (int*)(sm + OFF_SIDX);

    CP_WAIT0();
    __syncthreads();                  // raw0 + W visible

    // ---- hoist B (W^T) fragments into registers: LOOP-INVARIANT ----
    uint32_t bhr[8][4], blr[8][4];    // [ks*2+nb]
#pragma unroll
    for (int ks = 0; ks < 4; ks++)
#pragma unroll
        for (int nb = 0; nb < 2; nb++) {
            int nrow = q * 32 + nb * 16 + ((lane >> 4) << 3) + (lane & 7);
            int kc   = ks * 2 + ((lane >> 3) & 1);
            uint32_t byte = (uint32_t)(nrow * 128 + kc * 16);
            uint32_t bd = sb + OFF_WHI + SWZ(byte);
            LDMX4(bhr[ks * 2 + nb], bd);
            LDMX4(blr[ks * 2 + nb], bd + 16384);
        }

    convert_tile(sm, tid);
    __syncthreads();                  // conv visible (raw free)
    issue_cp(sm, sb, edge_attr, blockIdx.x + gridDim.x, E, n_tiles, tid);

    for (int mt = blockIdx.x; mt < n_tiles; mt += gridDim.x) {
        const int nE_cur = min(TM, E - mt * TM);

        // ---- endpoint indices + degree (one writer per endpoint) ----
        if (tid < 2 * TM) {
            int which = tid >> 6, e = tid & 63;
            int ge = mt * TM + e;
            int v = -1;
            if (ge < E) v = eidx[which * E + ge];
            sidx[tid] = v;
            if ((unsigned)v < (unsigned)n_nodes)
                atomicAdd(&g_degree[(unsigned)v], 1.f);
        }

        // ====== GEMM: warp (g,q) -> edges [32g,32g+32) x ch [32q,32q+32) =====
        float cfr[8][4];              // [(m*2+nb)*2+n8]
#pragma unroll
        for (int i = 0; i < 8; i++) {
            cfr[i][0] = 0.f; cfr[i][1] = 0.f; cfr[i][2] = 0.f; cfr[i][3] = 0.f;
        }
#pragma unroll
        for (int ks = 0; ks < 4; ks++) {
#pragma unroll
            for (int m = 0; m < 2; m++) {
                uint32_t ahi[4], alo[4];
                int arow = g * 32 + m * 16 + (lane & 15);
                uint32_t byte = (uint32_t)(arow * 128 + (ks * 2 + (lane >> 4)) * 16);
                uint32_t ad = sb + OFF_CONV + SWZ(byte);
                LDMX4(ahi, ad);
                LDMX4(alo, ad + APART);
#pragma unroll
                for (int nb = 0; nb < 2; nb++) {
                    const int bi = ks * 2 + nb;
                    const int ci = (m * 2 + nb) * 2;
                    MMA16816(cfr[ci],     ahi, bhr[bi][0], bhr[bi][1]);  // hi*hi
                    MMA16816(cfr[ci],     ahi, blr[bi][0], blr[bi][1]);  // hi*lo
                    MMA16816(cfr[ci],     alo, bhr[bi][0], bhr[bi][1]);  // lo*hi
                    MMA16816(cfr[ci + 1], ahi, bhr[bi][2], bhr[bi][3]);
                    MMA16816(cfr[ci + 1], ahi, blr[bi][2], blr[bi][3]);
                    MMA16816(cfr[ci + 1], alo, bhr[bi][2], bhr[bi][3]);
                }
            }
        }

        // ====== bias + relu + per-row partial sums (4 row-groups) ======
        float s[4]  = {0.f, 0.f, 0.f, 0.f};
        float s2[4] = {0.f, 0.f, 0.f, 0.f};
        const int colbase = (lane & 3) * 2;
#pragma unroll
        for (int m = 0; m < 2; m++)
#pragma unroll
            for (int nb = 0; nb < 2; nb++)
#pragma unroll
                for (int n8 = 0; n8 < 2; n8++) {
                    const int ci = (m * 2 + nb) * 2 + n8;
                    float2 bb = *(const float2*)(smbias + q * 32 + nb * 16 + n8 * 8 + colbase);
                    float v0 = fmaxf(cfr[ci][0] + bb.x, 0.f);
                    float v1 = fmaxf(cfr[ci][1] + bb.y, 0.f);
                    float v2 = fmaxf(cfr[ci][2] + bb.x, 0.f);
                    float v3 = fmaxf(cfr[ci][3] + bb.y, 0.f);
                    cfr[ci][0] = v0; cfr[ci][1] = v1; cfr[ci][2] = v2; cfr[ci][3] = v3;
                    s[m * 2 + 0]  += v0 + v1; s2[m * 2 + 0] += v0 * v0 + v1 * v1;
                    s[m * 2 + 1]  += v2 + v3; s2[m * 2 + 1] += v2 * v2 + v3 * v3;
                }
#pragma unroll
        for (int o = 1; o <= 2; o <<= 1)
#pragma unroll
            for (int rg = 0; rg < 4; rg++) {
                s[rg]  += __shfl_xor_sync(0xFFFFFFFFu, s[rg],  o);
                s2[rg] += __shfl_xor_sync(0xFFFFFFFFu, s2[rg], o);
            }
        // publish partials: spart[row][q]
        if ((lane & 3) == 0) {
#pragma unroll
            for (int rg = 0; rg < 4; rg++) {
                int row = g * 32 + (rg >> 1) * 16 + (rg & 1) * 8 + (lane >> 2);
                *(float2*)(spartf + row * 8 + q * 2) = make_float2(s[rg], s2[rg]);
            }
        }
        asm volatile("bar.sync %0, 128;" :: "r"(1 + g) : "memory");
        float mu[4], rin[4];
#pragma unroll
        for (int rg = 0; rg < 4; rg++) {
            int row = g * 32 + (rg >> 1) * 16 + (rg & 1) * 8 + (lane >> 2);
            float4 p0 = *(float4*)(spartf + row * 8);
            float4 p1 = *(float4*)(spartf + row * 8 + 4);
            float ss  = p0.x + p0.z + p1.x + p1.z;
            float ss2 = p0.y + p0.w + p1.y + p1.w;
            mu[rg] = ss * (1.f / NDIM);
            float var = ss2 * (1.f / NDIM) - mu[rg] * mu[rg];
            rin[rg] = rsqrtf(var + LN_EPS);
        }

        // normalized -> sh (swizzled float2 cols)
#pragma unroll
        for (int m = 0; m < 2; m++)
#pragma unroll
            for (int nb = 0; nb < 2; nb++)
#pragma unroll
                for (int n8 = 0; n8 < 2; n8++) {
                    const int ci = (m * 2 + nb) * 2 + n8;
                    const int j = q * 16 + nb * 8 + n8 * 4 + (lane & 3);
                    int rlo = g * 32 + m * 16 + (lane >> 2);
                    int rhi = rlo + 8;
                    int glo = m * 2, ghi = m * 2 + 1;
                    float2 va = make_float2((cfr[ci][0] - mu[glo]) * rin[glo],
                                            (cfr[ci][1] - mu[glo]) * rin[glo]);
                    float2 vb = make_float2((cfr[ci][2] - mu[ghi]) * rin[ghi],
                                            (cfr[ci][3] - mu[ghi]) * rin[ghi]);
                    *(float2*)(shp + rlo * NDIM + 2 * (j ^ ((rlo & 7) << 3))) = va;
                    *(float2*)(shp + rhi * NDIM + 2 * (j ^ ((rhi & 7) << 3))) = vb;
                }
        __syncthreads();                       // (A) sh + sidx ready; conv free

        // ====== edge-major scatter: read row once, RED to both endpoints =====
#pragma unroll
        for (int i = 0; i < 8; i++) {
            int e = warp * 8 + i;
            if (e < nE_cur) {
                unsigned n0 = (unsigned)sidx[e];
                unsigned n1 = (unsigned)sidx[64 + e];
                float4 v = ((float4*)(shp + e * NDIM))[lane ^ ((e & 7) << 2)];
                float4 vv;
                vv.x = v.x * g4.x + bt4.x;
                vv.y = v.y * g4.y + bt4.y;
                vv.z = v.z * g4.z + bt4.z;
                vv.w = v.w * g4.w + bt4.w;
                if (n0 < (unsigned)n_nodes) RED4(out + (long long)n0 * NDIM + 4 * lane, vv);
                if (n1 < (unsigned)n_nodes) RED4(out + (long long)n1 * NDIM + 4 * lane, vv);
            }
        }

        // ====== pipeline advance: convert t+1 into conv, launch t+2 ==========
        if (mt + gridDim.x < n_tiles) {
            CP_WAIT0();                         // raw(t+1) landed
            convert_tile(sm, tid);
        }
        __syncthreads();                        // (B) conv/scatter/sh settled
        issue_cp(sm, sb, edge_attr, mt + 2 * gridDim.x, E, n_tiles, tid);
    }
}

__global__ void finalize_kernel(float4* __restrict__ out, int n_nodes) {
    const int total = n_nodes * (NDIM / 4);
    int i = blockIdx.x * blockDim.x + threadIdx.x;
    int stride = gridDim.x * blockDim.x;
    for (int j = i; j < total; j += stride) {
        int node = j >> 5;
        float d = fmaxf(g_degree[node], 1.f);
        float inv = 1.f / d;
        float4 v = out[j];
        v.x *= inv; v.y *= inv; v.z *= inv; v.w *= inv;
        out[j] = v;
    }
}

extern "C" void kernel_launch(void* const* d_in, const int* in_sizes, int n_in,
                              void* d_out, int out_size) {
    // ---- resolve inputs by element count (order-permutation-proof) ----
    int ia = 0;
    for (int i = 1; i < n_in; i++)
        if (in_sizes[i] > in_sizes[ia]) ia = i;
    const float* edge_attr = (const float*)d_in[ia];
    const int E = in_sizes[ia] / EDIM;

    const float *W = 0, *b = 0, *gma = 0, *bta = 0;
    const int* eidx = 0;
    for (int i = 0; i < n_in; i++) {
        if (i == ia) continue;
        int s = in_sizes[i];
        if (s == EDIM * NDIM)      W = (const float*)d_in[i];
        else if (s == 2 * E)       eidx = (const int*)d_in[i];
        else if (s == NDIM) {
            if (!b)        b   = (const float*)d_in[i];
            else if (!gma) gma = (const float*)d_in[i];
            else           bta = (const float*)d_in[i];
        }
    }
    float* out = (float*)d_out;
    int n_nodes = out_size / NDIM;
    if (n_nodes > MAXNODES) n_nodes = MAXNODES;

    zero_kernel<<<2048, 256>>>((float4*)out, out_size / 4, n_nodes);

    // two noops: ncu capture profiles launch index 3 -> edge_kernel
    noop_kernel<<<1, 32>>>();
    noop_kernel<<<1, 32>>>();

    static int smem_set = 0;
    if (!smem_set) {
        cudaFuncSetAttribute(edge_kernel,
                             cudaFuncAttributeMaxDynamicSharedMemorySize, SMEM_TOTAL);
        smem_set = 1;
    }
    const int n_tiles = (E + TM - 1) / TM;
    int grid = 2 * 148;
    if (grid > n_tiles) grid = n_tiles;
    edge_kernel<<<grid, THREADS, SMEM_TOTAL>>>(edge_attr, W, b, gma, bta, eidx,
                                               out, E, n_nodes);

    finalize_kernel<<<1024, 256>>>((float4*)out, n_nodes);
}

// round 15
// speedup vs baseline: 1.6015x; 1.0530x over previous
#include <cuda_runtime.h>
#include <cuda_fp16.h>
#include <cstdint>

#define EDIM 64
#define NDIM 128
#define TM   64             // edges per tile
#define THREADS 256
#define MAXNODES 65536
#define LN_EPS 1e-5f

// ---- dynamic smem layout (bytes) ----
#define OFF_WHI   0         // W^T hi (fp16): 128 n-rows x 128B
#define OFF_WLO   16384
#define OFF_CONV  32768     // conv A (single fp16 tile): 8192
#define OFF_RAW   49152     // raw fp32 tile: 16384
#define OFF_SH    65536     // float[64][128] normalized rows (swizzled)
#define OFF_SIDX  98304     // int[128]
#define OFF_BIAS  98816     // float[128]
#define OFF_SPART 99328     // float2[64][4] = 2048 B
#define SMEM_TOTAL 101376

#define SWZ(x) ((x) ^ (((x) >> 3) & 0x70))

#define LDMX4(r, addr) \
    asm volatile("ldmatrix.sync.aligned.m8n8.x4.shared.b16 {%0,%1,%2,%3}, [%4];" \
        : "=r"((r)[0]), "=r"((r)[1]), "=r"((r)[2]), "=r"((r)[3]) : "r"(addr))

#define MMA16816(c, a, b0, b1) \
    asm volatile("mma.sync.aligned.m16n8k16.row.col.f32.f16.f16.f32 " \
        "{%0,%1,%2,%3}, {%4,%5,%6,%7}, {%8,%9}, {%0,%1,%2,%3};" \
        : "+f"((c)[0]), "+f"((c)[1]), "+f"((c)[2]), "+f"((c)[3]) \
        : "r"((a)[0]), "r"((a)[1]), "r"((a)[2]), "r"((a)[3]), "r"(b0), "r"(b1))

#define RED4(ptr, v) \
    asm volatile("red.global.add.v4.f32 [%0], {%1,%2,%3,%4};" \
                 :: "l"(ptr), "f"((v).x), "f"((v).y), "f"((v).z), "f"((v).w) : "memory")

#define CPASYNC16(dst, src) \
    asm volatile("cp.async.cg.shared.global [%0], [%1], 16;" \
                 :: "r"(dst), "l"(src) : "memory")
#define CP_COMMIT()  asm volatile("cp.async.commit_group;" ::: "memory")
#define CP_WAIT0()   asm volatile("cp.async.wait_group 0;" ::: "memory")

__device__ __forceinline__ uint32_t smem_u32(const void* p) {
    uint32_t a;
    asm("{ .reg .u64 t; cvta.to.shared.u64 t, %1; cvt.u32.u64 %0, t; }" : "=r"(a) : "l"(p));
    return a;
}
__device__ __forceinline__ uint32_t h2u(__half2 h) {
    return *reinterpret_cast<uint32_t*>(&h);
}

__device__ float g_degree[MAXNODES];

__global__ void zero_kernel(float4* __restrict__ out, int n_out4, int n_nodes) {
    int i = blockIdx.x * blockDim.x + threadIdx.x;
    int stride = gridDim.x * blockDim.x;
    float4 z = make_float4(0.f, 0.f, 0.f, 0.f);
    for (int j = i; j < n_out4; j += stride) out[j] = z;
    for (int j = i; j < n_nodes; j += stride) g_degree[j] = 0.f;
}
__global__ void noop_kernel() {}

// issue cp.async of raw fp32 tile tt (zero-fill tails)
__device__ __forceinline__ void issue_cp(
    char* sm, uint32_t sb, const float* __restrict__ edge_attr,
    int tt, int E, int n_tiles, int tid)
{
    if (tt >= n_tiles) return;
    const int base = tt * TM;
#pragma unroll
    for (int i = 0; i < 4; i++) {
        int idx = tid + THREADS * i;          // 0..1023 float4 slots (16/edge)
        int e = idx >> 4, k4 = idx & 15;
        if (base + e < E) {
            CPASYNC16(sb + OFF_RAW + idx * 16,
                      edge_attr + (long long)(base + e) * EDIM + k4 * 4);
        } else {
            *(uint4*)(sm + OFF_RAW + idx * 16) = make_uint4(0u, 0u, 0u, 0u);
        }
    }
    CP_COMMIT();
}

// convert raw fp32 tile -> single fp16 tile (SWZ layout)
__device__ __forceinline__ void convert_tile(char* sm, int tid) {
    const float* raw = (const float*)(sm + OFF_RAW);
    char* chi = sm + OFF_CONV;
#pragma unroll
    for (int i = 0; i < 2; i++) {
        int c = tid + THREADS * i;            // 0..511 chunks of 8 floats
        int e = c >> 3, k8 = c & 7;
        const float4* p = (const float4*)(raw + e * EDIM + k8 * 8);
        float4 f0 = p[0], f1 = p[1];
        __half2 v0 = __floats2half2_rn(f0.x, f0.y);
        __half2 v1 = __floats2half2_rn(f0.z, f0.w);
        __half2 v2 = __floats2half2_rn(f1.x, f1.y);
        __half2 v3 = __floats2half2_rn(f1.z, f1.w);
        uint32_t sw = SWZ((uint32_t)(e * 128 + k8 * 16));
        *(uint4*)(chi + sw) = make_uint4(h2u(v0), h2u(v1), h2u(v2), h2u(v3));
    }
}

extern "C" __global__ void __launch_bounds__(THREADS, 2)
edge_kernel(const float* __restrict__ edge_attr,
            const float* __restrict__ W,
            const float* __restrict__ b,
            const float* __restrict__ gamma,
            const float* __restrict__ beta,
            const int* __restrict__ eidx,
            float* __restrict__ out,
            int E, int n_nodes)
{
    extern __shared__ __align__(1024) char sm[];
    const uint32_t sb = smem_u32(sm);
    const int tid  = threadIdx.x;
    const int lane = tid & 31;
    const int warp = tid >> 5;        // 0..7
    const int g    = warp >> 2;       // m-group: edges [32g, 32g+32)
    const int q    = warp & 3;        // n-quarter: channels [32q, 32q+32)
    const int n_tiles = (E + TM - 1) / TM;

    // ---- pipeline prologue: first raw tile in flight during W staging ----
    issue_cp(sm, sb, edge_attr, blockIdx.x, E, n_tiles, tid);

    // ---- stage W^T hi/lo (fp16 split: w = hi + lo to ~2^-22) + bias ----
#pragma unroll
    for (int i = 0; i < 32; i++) {
        int j = tid + THREADS * i;           // j = k*128 + n (coalesced)
        int k = j >> 7, n = j & 127;
        float w = W[j];
        __half hi = __float2half_rn(w);
        __half lo = __float2half_rn(w - __half2float(hi));
        uint32_t sw = SWZ((uint32_t)(n * 128 + k * 2));
        *(__half*)(sm + OFF_WHI + sw) = hi;
        *(__half*)(sm + OFF_WLO + sw) = lo;
    }
    if (tid < NDIM) ((float*)(sm + OFF_BIAS))[tid] = b[tid];

    const float4 g4  = ((const float4*)gamma)[lane];
    const float4 bt4 = ((const float4*)beta)[lane];
    const float* smbias = (const float*)(sm + OFF_BIAS);
    float* shp = (float*)(sm + OFF_SH);
    float* spartf = (float*)(sm + OFF_SPART);   // float2[64][4] as floats
    int* sidx = (int*)(sm + OFF_SIDX);

    CP_WAIT0();
    __syncthreads();                  // raw0 + W visible

    // ---- hoist B (W^T) fragments into registers: LOOP-INVARIANT ----
    uint32_t bhr[8][4], blr[8][4];    // [ks*2+nb]
#pragma unroll
    for (int ks = 0; ks < 4; ks++)
#pragma unroll
        for (int nb = 0; nb < 2; nb++) {
            int nrow = q * 32 + nb * 16 + ((lane >> 4) << 3) + (lane & 7);
            int kc   = ks * 2 + ((lane >> 3) & 1);
            uint32_t byte = (uint32_t)(nrow * 128 + kc * 16);
            uint32_t bd = sb + OFF_WHI + SWZ(byte);
            LDMX4(bhr[ks * 2 + nb], bd);
            LDMX4(blr[ks * 2 + nb], bd + 16384);
        }

    convert_tile(sm, tid);
    __syncthreads();                  // conv visible (raw free)
    issue_cp(sm, sb, edge_attr, blockIdx.x + gridDim.x, E, n_tiles, tid);

    for (int mt = blockIdx.x; mt < n_tiles; mt += gridDim.x) {
        const int nE_cur = min(TM, E - mt * TM);

        // ---- endpoint indices + degree (one writer per endpoint) ----
        if (tid < 2 * TM) {
            int which = tid >> 6, e = tid & 63;
            int ge = mt * TM + e;
            int v = -1;
            if (ge < E) v = eidx[which * E + ge];
            sidx[tid] = v;
            if ((unsigned)v < (unsigned)n_nodes)
                atomicAdd(&g_degree[(unsigned)v], 1.f);
        }

        // ====== GEMM: warp (g,q) -> edges [32g,32g+32) x ch [32q,32q+32) =====
        // 2-term fp16: a * (w_hi + w_lo)
        float cfr[8][4];              // [(m*2+nb)*2+n8]
#pragma unroll
        for (int i = 0; i < 8; i++) {
            cfr[i][0] = 0.f; cfr[i][1] = 0.f; cfr[i][2] = 0.f; cfr[i][3] = 0.f;
        }
#pragma unroll
        for (int ks = 0; ks < 4; ks++) {
#pragma unroll
            for (int m = 0; m < 2; m++) {
                uint32_t ah[4];
                int arow = g * 32 + m * 16 + (lane & 15);
                uint32_t byte = (uint32_t)(arow * 128 + (ks * 2 + (lane >> 4)) * 16);
                LDMX4(ah, sb + OFF_CONV + SWZ(byte));
#pragma unroll
                for (int nb = 0; nb < 2; nb++) {
                    const int bi = ks * 2 + nb;
                    const int ci = (m * 2 + nb) * 2;
                    MMA16816(cfr[ci],     ah, bhr[bi][0], bhr[bi][1]);  // a*w_hi
                    MMA16816(cfr[ci],     ah, blr[bi][0], blr[bi][1]);  // a*w_lo
                    MMA16816(cfr[ci + 1], ah, bhr[bi][2], bhr[bi][3]);
                    MMA16816(cfr[ci + 1], ah, blr[bi][2], blr[bi][3]);
                }
            }
        }

        // ====== bias + relu + per-row partial sums (4 row-groups) ======
        float s[4]  = {0.f, 0.f, 0.f, 0.f};
        float s2[4] = {0.f, 0.f, 0.f, 0.f};
        const int colbase = (lane & 3) * 2;
#pragma unroll
        for (int m = 0; m < 2; m++)
#pragma unroll
            for (int nb = 0; nb < 2; nb++)
#pragma unroll
                for (int n8 = 0; n8 < 2; n8++) {
                    const int ci = (m * 2 + nb) * 2 + n8;
                    float2 bb = *(const float2*)(smbias + q * 32 + nb * 16 + n8 * 8 + colbase);
                    float v0 = fmaxf(cfr[ci][0] + bb.x, 0.f);
                    float v1 = fmaxf(cfr[ci][1] + bb.y, 0.f);
                    float v2 = fmaxf(cfr[ci][2] + bb.x, 0.f);
                    float v3 = fmaxf(cfr[ci][3] + bb.y, 0.f);
                    cfr[ci][0] = v0; cfr[ci][1] = v1; cfr[ci][2] = v2; cfr[ci][3] = v3;
                    s[m * 2 + 0]  += v0 + v1; s2[m * 2 + 0] += v0 * v0 + v1 * v1;
                    s[m * 2 + 1]  += v2 + v3; s2[m * 2 + 1] += v2 * v2 + v3 * v3;
                }
#pragma unroll
        for (int o = 1; o <= 2; o <<= 1)
#pragma unroll
            for (int rg = 0; rg < 4; rg++) {
                s[rg]  += __shfl_xor_sync(0xFFFFFFFFu, s[rg],  o);
                s2[rg] += __shfl_xor_sync(0xFFFFFFFFu, s2[rg], o);
            }
        // publish partials: spart[row][q]
        if ((lane & 3) == 0) {
#pragma unroll
            for (int rg = 0; rg < 4; rg++) {
                int row = g * 32 + (rg >> 1) * 16 + (rg & 1) * 8 + (lane >> 2);
                *(float2*)(spartf + row * 8 + q * 2) = make_float2(s[rg], s2[rg]);
            }
        }
        asm volatile("bar.sync %0, 128;" :: "r"(1 + g) : "memory");
        float mu[4], rin[4];
#pragma unroll
        for (int rg = 0; rg < 4; rg++) {
            int row = g * 32 + (rg >> 1) * 16 + (rg & 1) * 8 + (lane >> 2);
            float4 p0 = *(float4*)(spartf + row * 8);
            float4 p1 = *(float4*)(spartf + row * 8 + 4);
            float ss  = p0.x + p0.z + p1.x + p1.z;
            float ss2 = p0.y + p0.w + p1.y + p1.w;
            mu[rg] = ss * (1.f / NDIM);
            float var = ss2 * (1.f / NDIM) - mu[rg] * mu[rg];
            rin[rg] = rsqrtf(var + LN_EPS);
        }

        // normalized -> sh (swizzled float2 cols)
#pragma unroll
        for (int m = 0; m < 2; m++)
#pragma unroll
            for (int nb = 0; nb < 2; nb++)
#pragma unroll
                for (int n8 = 0; n8 < 2; n8++) {
                    const int ci = (m * 2 + nb) * 2 + n8;
                    const int j = q * 16 + nb * 8 + n8 * 4 + (lane & 3);
                    int rlo = g * 32 + m * 16 + (lane >> 2);
                    int rhi = rlo + 8;
                    int glo = m * 2, ghi = m * 2 + 1;
                    float2 va = make_float2((cfr[ci][0] - mu[glo]) * rin[glo],
                                            (cfr[ci][1] - mu[glo]) * rin[glo]);
                    float2 vb = make_float2((cfr[ci][2] - mu[ghi]) * rin[ghi],
                                            (cfr[ci][3] - mu[ghi]) * rin[ghi]);
                    *(float2*)(shp + rlo * NDIM + 2 * (j ^ ((rlo & 7) << 3))) = va;
                    *(float2*)(shp + rhi * NDIM + 2 * (j ^ ((rhi & 7) << 3))) = vb;
                }
        __syncthreads();                       // (A) sh + sidx ready; conv free

        // ====== edge-major scatter: read row once, RED to both endpoints =====
#pragma unroll
        for (int i = 0; i < 8; i++) {
            int e = warp * 8 + i;
            if (e < nE_cur) {
                unsigned n0 = (unsigned)sidx[e];
                unsigned n1 = (unsigned)sidx[64 + e];
                float4 v = ((float4*)(shp + e * NDIM))[lane ^ ((e & 7) << 2)];
                float4 vv;
                vv.x = v.x * g4.x + bt4.x;
                vv.y = v.y * g4.y + bt4.y;
                vv.z = v.z * g4.z + bt4.z;
                vv.w = v.w * g4.w + bt4.w;
                if (n0 < (unsigned)n_nodes) RED4(out + (long long)n0 * NDIM + 4 * lane, vv);
                if (n1 < (unsigned)n_nodes) RED4(out + (long long)n1 * NDIM + 4 * lane, vv);
            }
        }

        // ====== pipeline advance: convert t+1 into conv, launch t+2 ==========
        if (mt + gridDim.x < n_tiles) {
            CP_WAIT0();                         // raw(t+1) landed
            convert_tile(sm, tid);
        }
        __syncthreads();                        // (B) conv/scatter/sh settled
        issue_cp(sm, sb, edge_attr, mt + 2 * gridDim.x, E, n_tiles, tid);
    }
}

__global__ void finalize_kernel(float4* __restrict__ out, int n_nodes) {
    const int total = n_nodes * (NDIM / 4);
    int i = blockIdx.x * blockDim.x + threadIdx.x;
    int stride = gridDim.x * blockDim.x;
    for (int j = i; j < total; j += stride) {
        int node = j >> 5;
        float d = fmaxf(g_degree[node], 1.f);
        float inv = 1.f / d;
        float4 v = out[j];
        v.x *= inv; v.y *= inv; v.z *= inv; v.w *= inv;
        out[j] = v;
    }
}

extern "C" void kernel_launch(void* const* d_in, const int* in_sizes, int n_in,
                              void* d_out, int out_size) {
    // ---- resolve inputs by element count (order-permutation-proof) ----
    int ia = 0;
    for (int i = 1; i < n_in; i++)
        if (in_sizes[i] > in_sizes[ia]) ia = i;
    const float* edge_attr = (const float*)d_in[ia];
    const int E = in_sizes[ia] / EDIM;

    const float *W = 0, *b = 0, *gma = 0, *bta = 0;
    const int* eidx = 0;
    for (int i = 0; i < n_in; i++) {
        if (i == ia) continue;
        int s = in_sizes[i];
        if (s == EDIM * NDIM)      W = (const float*)d_in[i];
        else if (s == 2 * E)       eidx = (const int*)d_in[i];
        else if (s == NDIM) {
            if (!b)        b   = (const float*)d_in[i];
            else if (!gma) gma = (const float*)d_in[i];
            else           bta = (const float*)d_in[i];
        }
    }
    float* out = (float*)d_out;
    int n_nodes = out_size / NDIM;
    if (n_nodes > MAXNODES) n_nodes = MAXNODES;

    zero_kernel<<<2048, 256>>>((float4*)out, out_size / 4, n_nodes);

    // two noops: ncu capture profiles launch index 3 -> edge_kernel
    noop_kernel<<<1, 32>>>();
    noop_kernel<<<1, 32>>>();

    static int smem_set = 0;
    if (!smem_set) {
        cudaFuncSetAttribute(edge_kernel,
                             cudaFuncAttributeMaxDynamicSharedMemorySize, SMEM_TOTAL);
        smem_set = 1;
    }
    const int n_tiles = (E + TM - 1) / TM;
    int grid = 2 * 148;
    if (grid > n_tiles) grid = n_tiles;
    edge_kernel<<<grid, THREADS, SMEM_TOTAL>>>(edge_attr, W, b, gma, bta, eidx,
                                               out, E, n_nodes);

    finalize_kernel<<<1024, 256>>>((float4*)out, n_nodes);
}